// round 8
// baseline (speedup 1.0000x reference)
#include <cuda_runtime.h>
#include <cuda_bf16.h>

typedef unsigned long long u64;

#define NLEVELS 16
#define TSIZE   (1u << 19)
#define HIDDEN  32
#define NPTS_MAX 2000000
#define CELL_BITS 7
#define CELLS_AXIS (1 << CELL_BITS)
#define NCELLS (1u << (3 * CELL_BITS))
#define SCAN_BLK 1024
#define NPART (NCELLS / SCAN_BLK)

// ---- static scratch ----
__device__ unsigned g_cell_count[NCELLS];
__device__ unsigned g_cell_start[NCELLS];
__device__ unsigned g_partials[NPART];
__device__ float4   g_pts[NPTS_MAX];

__constant__ float c_scales[NLEVELS] = {
    15.0f, 19.158736798317971f, 24.398416831491190f, 31.0f,
    39.317473596635942f, 49.796833662982379f, 63.0f, 79.634947193271885f,
    100.59366732596476f, 127.0f, 160.26989438654377f, 202.18733465192952f,
    255.0f, 321.53978877308754f, 405.37466930385904f, 511.0f
};

// ---- packed f32x2 helpers ----
__device__ __forceinline__ u64 pack2(float lo, float hi) {
    u64 r; asm("mov.b64 %0, {%1, %2};" : "=l"(r) : "f"(lo), "f"(hi)); return r;
}
__device__ __forceinline__ void unpack2(u64 v, float& lo, float& hi) {
    asm("mov.b64 {%0, %1}, %2;" : "=f"(lo), "=f"(hi) : "l"(v));
}
__device__ __forceinline__ u64 ffma2(u64 a, u64 b, u64 c) {
    u64 d; asm("fma.rn.f32x2 %0, %1, %2, %3;" : "=l"(d) : "l"(a), "l"(b), "l"(c)); return d;
}

__device__ __forceinline__ unsigned expand3(unsigned v) {
    v &= 0x3FFu;
    v = (v | (v << 16)) & 0x030000FFu;
    v = (v | (v << 8))  & 0x0300F00Fu;
    v = (v | (v << 4))  & 0x030C30C3u;
    v = (v | (v << 2))  & 0x09249249u;
    return v;
}

__device__ __forceinline__ unsigned cell_code(float xn0, float xn1, float xn2) {
    int c0 = min(CELLS_AXIS - 1, max(0, (int)(xn0 * (float)CELLS_AXIS)));
    int c1 = min(CELLS_AXIS - 1, max(0, (int)(xn1 * (float)CELLS_AXIS)));
    int c2 = min(CELLS_AXIS - 1, max(0, (int)(xn2 * (float)CELLS_AXIS)));
    return expand3((unsigned)c0) | (expand3((unsigned)c1) << 1) | (expand3((unsigned)c2) << 2);
}

// ---- sort pipeline ----
__global__ void zero_counts_kernel() {
    unsigned i = blockIdx.x * blockDim.x + threadIdx.x;
    reinterpret_cast<uint4*>(g_cell_count)[i] = make_uint4(0u, 0u, 0u, 0u);
}

__global__ void hist_kernel(const float* __restrict__ x, int n) {
    int i = blockIdx.x * blockDim.x + threadIdx.x;
    if (i >= n) return;
    const float xn0 = (x[3 * i + 0] + 1.0f) * 0.5f;
    const float xn1 = (x[3 * i + 1] + 1.0f) * 0.5f;
    const float xn2 = (x[3 * i + 2] + 1.0f) * 0.5f;
    atomicAdd(&g_cell_count[cell_code(xn0, xn1, xn2)], 1u);
}

__device__ __forceinline__ unsigned block_incl_scan(unsigned v, unsigned tid) {
    __shared__ unsigned warp_sums[32];
    unsigned inc = v;
    #pragma unroll
    for (int off = 1; off < 32; off <<= 1) {
        unsigned t = __shfl_up_sync(~0u, inc, off);
        if ((tid & 31u) >= (unsigned)off) inc += t;
    }
    if ((tid & 31u) == 31u) warp_sums[tid >> 5] = inc;
    __syncthreads();
    if (tid < 32) {
        unsigned s = warp_sums[tid];
        #pragma unroll
        for (int off = 1; off < 32; off <<= 1) {
            unsigned t = __shfl_up_sync(~0u, s, off);
            if (tid >= (unsigned)off) s += t;
        }
        warp_sums[tid] = s;
    }
    __syncthreads();
    unsigned base = (tid >= 32u) ? warp_sums[(tid >> 5) - 1u] : 0u;
    return base + inc;
}

__global__ void scan1_kernel() {
    const unsigned tid = threadIdx.x;
    const unsigned g = blockIdx.x * SCAN_BLK + tid;
    const unsigned v = g_cell_count[g];
    const unsigned inc = block_incl_scan(v, tid);
    g_cell_start[g] = inc - v;
    if (tid == SCAN_BLK - 1) g_partials[blockIdx.x] = inc;
}

__global__ void scan2_kernel() {
    const unsigned tid = threadIdx.x;
    const unsigned a = g_partials[2 * tid];
    const unsigned b = g_partials[2 * tid + 1];
    const unsigned s = a + b;
    const unsigned inc = block_incl_scan(s, tid);
    const unsigned excl = inc - s;
    g_partials[2 * tid]     = excl;
    g_partials[2 * tid + 1] = excl + a;
}

__global__ void scan3_kernel() {
    const unsigned g = blockIdx.x * SCAN_BLK + threadIdx.x;
    g_cell_start[g] += g_partials[blockIdx.x];
}

__global__ void scatter_kernel(const float* __restrict__ x, int n) {
    int i = blockIdx.x * blockDim.x + threadIdx.x;
    if (i >= n) return;
    const float xn0 = (x[3 * i + 0] + 1.0f) * 0.5f;
    const float xn1 = (x[3 * i + 1] + 1.0f) * 0.5f;
    const float xn2 = (x[3 * i + 2] + 1.0f) * 0.5f;
    const unsigned pos = atomicAdd(&g_cell_start[cell_code(xn0, xn1, xn2)], 1u);
    g_pts[pos] = make_float4(xn0, xn1, xn2, __uint_as_float((unsigned)i));
}

// ---- per-point level gather: 4 x-merged corner pairs -> packed features ----
struct LevelHash {
    unsigned hx0, hx1, hyz[4];
    float wt0[4], wt1[4];     // weights for x=0 / x=1 corner of each yz pair
    bool  can;                // i0 even -> idx1 = idx0^1 (float4 merge)
};

__device__ __forceinline__ LevelHash make_level_hash(float x0, float x1, float x2, float s) {
    LevelHash lh;
    const float p0 = x0 * s, p1 = x1 * s, p2 = x2 * s;
    const float f0 = floorf(p0), f1 = floorf(p1), f2 = floorf(p2);
    const float w0 = p0 - f0, w1 = p1 - f1, w2 = p2 - f2;
    const unsigned i0 = (unsigned)f0, i1 = (unsigned)f1, i2 = (unsigned)f2;
    lh.hx0 = i0;
    lh.hx1 = i0 + 1u;
    const unsigned hy0 = i1 * 2654435761u, hy1 = (i1 + 1u) * 2654435761u;
    const unsigned hz0 = i2 * 805459861u,  hz1 = (i2 + 1u) * 805459861u;
    lh.hyz[0] = hy0 ^ hz0; lh.hyz[1] = hy1 ^ hz0;
    lh.hyz[2] = hy0 ^ hz1; lh.hyz[3] = hy1 ^ hz1;
    const float wy0 = 1.0f - w1, wz0 = 1.0f - w2;
    const float wyz0 = wy0 * wz0, wyz1 = w1 * wz0, wyz2 = wy0 * w2, wyz3 = w1 * w2;
    const float wx0 = 1.0f - w0;
    lh.wt0[0] = wx0 * wyz0; lh.wt1[0] = w0 * wyz0;
    lh.wt0[1] = wx0 * wyz1; lh.wt1[1] = w0 * wyz1;
    lh.wt0[2] = wx0 * wyz2; lh.wt1[2] = w0 * wyz2;
    lh.wt0[3] = wx0 * wyz3; lh.wt1[3] = w0 * wyz3;
    lh.can = (i0 & 1u) == 0u;
    return lh;
}

// gather one yz-pair (two x corners) for one point; returns (g0, g1)
__device__ __forceinline__ void gather_pair(const float2* __restrict__ tbl,
                                            const LevelHash& lh, int p,
                                            float2& g0, float2& g1) {
    const unsigned idx0 = (lh.hx0 ^ lh.hyz[p]) & (TSIZE - 1u);
    const float4 v = __ldg(reinterpret_cast<const float4*>(tbl) + (idx0 >> 1));
    const bool hi = (idx0 & 1u) != 0u;
    g0.x = hi ? v.z : v.x;  g0.y = hi ? v.w : v.y;
    g1.x = hi ? v.x : v.z;  g1.y = hi ? v.y : v.w;   // valid when lh.can
    if (!lh.can) {
        const unsigned idx1 = (lh.hx1 ^ lh.hyz[p]) & (TSIZE - 1u);
        g1 = __ldg(tbl + idx1);
    }
}

// ---- fused hash-encode + MLP, 2 points/thread (block-strided), packed f32x2 ----
__global__ __launch_bounds__(128)
void field_fused_kernel(const float* __restrict__ table,
                        const float* __restrict__ W0,
                        const float* __restrict__ b0,
                        const float* __restrict__ W1,
                        const float* __restrict__ b1,
                        const float* __restrict__ Wout,
                        const float* __restrict__ bout,
                        float* __restrict__ out,
                        int n)
{
    __shared__ u64 sW0[35 * 32];
    __shared__ u64 sW1[32 * 32];
    __shared__ u64 sb0[32];
    __shared__ u64 sb1[32];
    __shared__ u64 sWout[32];
    __shared__ float sbout;

    const int tid = threadIdx.x;
    for (int i = tid; i < 35 * 32; i += blockDim.x) { float w = W0[i]; sW0[i] = pack2(w, w); }
    for (int i = tid; i < 32 * 32; i += blockDim.x) { float w = W1[i]; sW1[i] = pack2(w, w); }
    if (tid < 32) {
        float v0 = b0[tid];   sb0[tid]   = pack2(v0, v0);
        float v1 = b1[tid];   sb1[tid]   = pack2(v1, v1);
        float vo = Wout[tid]; sWout[tid] = pack2(vo, vo);
    }
    if (tid == 0) sbout = bout[0];
    __syncthreads();

    // block-strided pairing: A = chunk[tid], B = chunk[tid + 128]
    const int base = blockIdx.x * 256;
    const int iA = base + tid;
    if (iA >= n) return;
    int iB = base + 128 + tid;
    const bool hasB = iB < n;
    if (!hasB) iB = iA;

    const float4 ptA = g_pts[iA];
    const float4 ptB = g_pts[iB];
    const unsigned oiA = __float_as_uint(ptA.w);
    const unsigned oiB = __float_as_uint(ptB.w);

    const u64 xp0 = pack2(ptA.x, ptB.x);
    const u64 xp1 = pack2(ptA.y, ptB.y);
    const u64 xp2 = pack2(ptA.z, ptB.z);

    u64 h[HIDDEN];
    #pragma unroll
    for (int j = 0; j < HIDDEN; j++) {
        h[j] = ffma2(xp0, sW0[0 * 32 + j],
               ffma2(xp1, sW0[1 * 32 + j],
               ffma2(xp2, sW0[2 * 32 + j], sb0[j])));
    }

    #pragma unroll 4
    for (int l = 0; l < NLEVELS; l++) {
        const float s = c_scales[l];
        const float2* __restrict__ tbl =
            reinterpret_cast<const float2*>(table) + (size_t)l * TSIZE;

        const LevelHash lhA = make_level_hash(ptA.x, ptA.y, ptA.z, s);
        const LevelHash lhB = make_level_hash(ptB.x, ptB.y, ptB.z, s);

        u64 a0 = 0ull, a1 = 0ull;
        #pragma unroll
        for (int p = 0; p < 4; p++) {
            float2 gA0, gA1, gB0, gB1;
            gather_pair(tbl, lhA, p, gA0, gA1);
            gather_pair(tbl, lhB, p, gB0, gB1);
            const u64 w0p = pack2(lhA.wt0[p], lhB.wt0[p]);
            const u64 w1p = pack2(lhA.wt1[p], lhB.wt1[p]);
            a0 = ffma2(w0p, pack2(gA0.x, gB0.x), a0);
            a1 = ffma2(w0p, pack2(gA0.y, gB0.y), a1);
            a0 = ffma2(w1p, pack2(gA1.x, gB1.x), a0);
            a1 = ffma2(w1p, pack2(gA1.y, gB1.y), a1);
        }

        const u64* wr0 = &sW0[(3 + 2 * l) * 32];
        const u64* wr1 = &sW0[(4 + 2 * l) * 32];
        #pragma unroll
        for (int j = 0; j < HIDDEN; j++) {
            h[j] = ffma2(a0, wr0[j], ffma2(a1, wr1[j], h[j]));
        }
    }

    #pragma unroll
    for (int j = 0; j < HIDDEN; j++) {
        float a, b;
        unpack2(h[j], a, b);
        a = a > 0.0f ? a : expm1f(a);
        b = b > 0.0f ? b : expm1f(b);
        h[j] = pack2(a, b);
    }

    u64 o = pack2(sbout, sbout);
    #pragma unroll 4
    for (int j = 0; j < HIDDEN; j++) {
        u64 t = sb1[j];
        #pragma unroll
        for (int i = 0; i < HIDDEN; i++) {
            t = ffma2(h[i], sW1[i * 32 + j], t);
        }
        float a, b;
        unpack2(t, a, b);
        a = a > 0.0f ? a : expm1f(a);
        b = b > 0.0f ? b : expm1f(b);
        o = ffma2(pack2(a, b), sWout[j], o);
    }

    float oA, oB;
    unpack2(o, oA, oB);
    out[oiA] = oA;
    if (hasB) out[oiB] = oB;
}

extern "C" void kernel_launch(void* const* d_in, const int* in_sizes, int n_in,
                              void* d_out, int out_size)
{
    const float* x     = (const float*)d_in[0];
    const float* table = (const float*)d_in[1];
    const float* W0    = (const float*)d_in[2];
    const float* b0    = (const float*)d_in[3];
    const float* W1    = (const float*)d_in[4];
    const float* b1    = (const float*)d_in[5];
    const float* Wout  = (const float*)d_in[6];
    const float* bout  = (const float*)d_in[7];
    float* out = (float*)d_out;

    const int n = in_sizes[0] / 3;

    zero_counts_kernel<<<NCELLS / 4 / 1024, 1024>>>();
    hist_kernel<<<(n + 255) / 256, 256>>>(x, n);
    scan1_kernel<<<NPART, SCAN_BLK>>>();
    scan2_kernel<<<1, SCAN_BLK>>>();
    scan3_kernel<<<NPART, SCAN_BLK>>>();
    scatter_kernel<<<(n + 255) / 256, 256>>>(x, n);

    const int nchunk = (n + 255) / 256;
    field_fused_kernel<<<nchunk, 128>>>(
        table, W0, b0, W1, b1, Wout, bout, out, n);
}

// round 9
// speedup vs baseline: 1.2078x; 1.2078x over previous
#include <cuda_runtime.h>
#include <cuda_bf16.h>

typedef unsigned long long u64;

#define NLEVELS 16
#define TSIZE   (1u << 19)
#define HIDDEN  32
#define NPTS_MAX 2000000
#define CELL_BITS 7
#define CELLS_AXIS (1 << CELL_BITS)
#define NCELLS (1u << (3 * CELL_BITS))
#define SCAN_BLK 1024
#define NPART (NCELLS / SCAN_BLK)

// ---- static scratch ----
__device__ unsigned g_cell_count[NCELLS];
__device__ unsigned g_cell_start[NCELLS];
__device__ unsigned g_partials[NPART];
__device__ float4   g_pts[NPTS_MAX];

__constant__ float c_scales[NLEVELS] = {
    15.0f, 19.158736798317971f, 24.398416831491190f, 31.0f,
    39.317473596635942f, 49.796833662982379f, 63.0f, 79.634947193271885f,
    100.59366732596476f, 127.0f, 160.26989438654377f, 202.18733465192952f,
    255.0f, 321.53978877308754f, 405.37466930385904f, 511.0f
};

// ---- packed f32x2 helpers ----
__device__ __forceinline__ u64 pack2(float lo, float hi) {
    u64 r; asm("mov.b64 %0, {%1, %2};" : "=l"(r) : "f"(lo), "f"(hi)); return r;
}
__device__ __forceinline__ void unpack2(u64 v, float& lo, float& hi) {
    asm("mov.b64 {%0, %1}, %2;" : "=f"(lo), "=f"(hi) : "l"(v));
}
__device__ __forceinline__ u64 ffma2(u64 a, u64 b, u64 c) {
    u64 d; asm("fma.rn.f32x2 %0, %1, %2, %3;" : "=l"(d) : "l"(a), "l"(b), "l"(c)); return d;
}

__device__ __forceinline__ unsigned expand3(unsigned v) {
    v &= 0x3FFu;
    v = (v | (v << 16)) & 0x030000FFu;
    v = (v | (v << 8))  & 0x0300F00Fu;
    v = (v | (v << 4))  & 0x030C30C3u;
    v = (v | (v << 2))  & 0x09249249u;
    return v;
}

__device__ __forceinline__ unsigned cell_code(float xn0, float xn1, float xn2) {
    int c0 = min(CELLS_AXIS - 1, max(0, (int)(xn0 * (float)CELLS_AXIS)));
    int c1 = min(CELLS_AXIS - 1, max(0, (int)(xn1 * (float)CELLS_AXIS)));
    int c2 = min(CELLS_AXIS - 1, max(0, (int)(xn2 * (float)CELLS_AXIS)));
    return expand3((unsigned)c0) | (expand3((unsigned)c1) << 1) | (expand3((unsigned)c2) << 2);
}

// ---- sort pipeline ----
__global__ void zero_counts_kernel() {
    unsigned i = blockIdx.x * blockDim.x + threadIdx.x;
    reinterpret_cast<uint4*>(g_cell_count)[i] = make_uint4(0u, 0u, 0u, 0u);
}

__global__ void hist_kernel(const float* __restrict__ x, int n) {
    int i = blockIdx.x * blockDim.x + threadIdx.x;
    if (i >= n) return;
    const float xn0 = (x[3 * i + 0] + 1.0f) * 0.5f;
    const float xn1 = (x[3 * i + 1] + 1.0f) * 0.5f;
    const float xn2 = (x[3 * i + 2] + 1.0f) * 0.5f;
    atomicAdd(&g_cell_count[cell_code(xn0, xn1, xn2)], 1u);
}

__device__ __forceinline__ unsigned block_incl_scan(unsigned v, unsigned tid) {
    __shared__ unsigned warp_sums[32];
    unsigned inc = v;
    #pragma unroll
    for (int off = 1; off < 32; off <<= 1) {
        unsigned t = __shfl_up_sync(~0u, inc, off);
        if ((tid & 31u) >= (unsigned)off) inc += t;
    }
    if ((tid & 31u) == 31u) warp_sums[tid >> 5] = inc;
    __syncthreads();
    if (tid < 32) {
        unsigned s = warp_sums[tid];
        #pragma unroll
        for (int off = 1; off < 32; off <<= 1) {
            unsigned t = __shfl_up_sync(~0u, s, off);
            if (tid >= (unsigned)off) s += t;
        }
        warp_sums[tid] = s;
    }
    __syncthreads();
    unsigned base = (tid >= 32u) ? warp_sums[(tid >> 5) - 1u] : 0u;
    return base + inc;
}

__global__ void scan1_kernel() {
    const unsigned tid = threadIdx.x;
    const unsigned g = blockIdx.x * SCAN_BLK + tid;
    const unsigned v = g_cell_count[g];
    const unsigned inc = block_incl_scan(v, tid);
    g_cell_start[g] = inc - v;
    if (tid == SCAN_BLK - 1) g_partials[blockIdx.x] = inc;
}

__global__ void scan2_kernel() {
    const unsigned tid = threadIdx.x;
    const unsigned a = g_partials[2 * tid];
    const unsigned b = g_partials[2 * tid + 1];
    const unsigned s = a + b;
    const unsigned inc = block_incl_scan(s, tid);
    const unsigned excl = inc - s;
    g_partials[2 * tid]     = excl;
    g_partials[2 * tid + 1] = excl + a;
}

__global__ void scan3_kernel() {
    const unsigned g = blockIdx.x * SCAN_BLK + threadIdx.x;
    g_cell_start[g] += g_partials[blockIdx.x];
}

__global__ void scatter_kernel(const float* __restrict__ x, int n) {
    int i = blockIdx.x * blockDim.x + threadIdx.x;
    if (i >= n) return;
    const float xn0 = (x[3 * i + 0] + 1.0f) * 0.5f;
    const float xn1 = (x[3 * i + 1] + 1.0f) * 0.5f;
    const float xn2 = (x[3 * i + 2] + 1.0f) * 0.5f;
    const unsigned pos = atomicAdd(&g_cell_start[cell_code(xn0, xn1, xn2)], 1u);
    g_pts[pos] = make_float4(xn0, xn1, xn2, __uint_as_float((unsigned)i));
}

// ---- fused hash-encode + MLP, 2 points per thread (block-strided pairing),
//      packed f32x2 math — otherwise identical to the 576us R3 kernel ----
__global__ __launch_bounds__(128)
void field_fused_kernel(const float* __restrict__ table,
                        const float* __restrict__ W0,
                        const float* __restrict__ b0,
                        const float* __restrict__ W1,
                        const float* __restrict__ b1,
                        const float* __restrict__ Wout,
                        const float* __restrict__ bout,
                        float* __restrict__ out,
                        int n)
{
    __shared__ u64 sW0[35 * 32];
    __shared__ u64 sW1[32 * 32];
    __shared__ u64 sb0[32];
    __shared__ u64 sb1[32];
    __shared__ u64 sWout[32];
    __shared__ float sbout;

    const int tid = threadIdx.x;
    for (int i = tid; i < 35 * 32; i += blockDim.x) { float w = W0[i]; sW0[i] = pack2(w, w); }
    for (int i = tid; i < 32 * 32; i += blockDim.x) { float w = W1[i]; sW1[i] = pack2(w, w); }
    if (tid < 32) {
        float v0 = b0[tid];   sb0[tid]   = pack2(v0, v0);
        float v1 = b1[tid];   sb1[tid]   = pack2(v1, v1);
        float vo = Wout[tid]; sWout[tid] = pack2(vo, vo);
    }
    if (tid == 0) sbout = bout[0];
    __syncthreads();

    // block-strided pairing over a 256-point chunk:
    // A = chunk[tid], B = chunk[tid + 128]. Each warp-instruction's 32 lanes
    // then span a 32-point sorted run (vs 64 with interleaved pairing).
    const int base = blockIdx.x * 256;
    const int iA = base + tid;
    if (iA >= n) return;
    int iB = base + 128 + tid;
    const bool hasB = iB < n;
    if (!hasB) iB = iA;

    const float4 ptA = g_pts[iA];
    const float4 ptB = g_pts[iB];
    const unsigned oiA = __float_as_uint(ptA.w);
    const unsigned oiB = __float_as_uint(ptB.w);

    const u64 xp0 = pack2(ptA.x, ptB.x);
    const u64 xp1 = pack2(ptA.y, ptB.y);
    const u64 xp2 = pack2(ptA.z, ptB.z);

    // ---- layer-0 accumulator (packed): bias + coords ----
    u64 h[HIDDEN];
    #pragma unroll
    for (int j = 0; j < HIDDEN; j++) {
        h[j] = ffma2(xp0, sW0[0 * 32 + j],
               ffma2(xp1, sW0[1 * 32 + j],
               ffma2(xp2, sW0[2 * 32 + j], sb0[j])));
    }

    // ---- hash-grid levels, folded into h ----
    #pragma unroll 4
    for (int l = 0; l < NLEVELS; l++) {
        const float s = c_scales[l];
        const float2* __restrict__ tbl =
            reinterpret_cast<const float2*>(table) + (size_t)l * TSIZE;

        // point A
        const float pA0 = ptA.x * s, pA1 = ptA.y * s, pA2 = ptA.z * s;
        const float fA0 = floorf(pA0), fA1 = floorf(pA1), fA2 = floorf(pA2);
        const float wA0 = pA0 - fA0, wA1 = pA1 - fA1, wA2 = pA2 - fA2;
        const unsigned iA0 = (unsigned)fA0, iA1 = (unsigned)fA1, iA2 = (unsigned)fA2;
        const unsigned hxA0 = iA0,            hxA1 = iA0 + 1u;
        const unsigned hyA0 = iA1 * 2654435761u, hyA1 = (iA1 + 1u) * 2654435761u;
        const unsigned hzA0 = iA2 * 805459861u,  hzA1 = (iA2 + 1u) * 805459861u;

        // point B
        const float pB0 = ptB.x * s, pB1 = ptB.y * s, pB2 = ptB.z * s;
        const float fB0 = floorf(pB0), fB1 = floorf(pB1), fB2 = floorf(pB2);
        const float wB0 = pB0 - fB0, wB1 = pB1 - fB1, wB2 = pB2 - fB2;
        const unsigned iB0 = (unsigned)fB0, iB1 = (unsigned)fB1, iB2 = (unsigned)fB2;
        const unsigned hxB0 = iB0,            hxB1 = iB0 + 1u;
        const unsigned hyB0 = iB1 * 2654435761u, hyB1 = (iB1 + 1u) * 2654435761u;
        const unsigned hzB0 = iB2 * 805459861u,  hzB1 = (iB2 + 1u) * 805459861u;

        u64 a0 = 0ull, a1 = 0ull;
        #pragma unroll
        for (int c = 0; c < 8; c++) {
            const unsigned idxA = (((c & 1) ? hxA1 : hxA0) ^ ((c & 2) ? hyA1 : hyA0)
                                 ^ ((c & 4) ? hzA1 : hzA0)) & (TSIZE - 1u);
            const unsigned idxB = (((c & 1) ? hxB1 : hxB0) ^ ((c & 2) ? hyB1 : hyB0)
                                 ^ ((c & 4) ? hzB1 : hzB0)) & (TSIZE - 1u);
            const float wtA = ((c & 1) ? wA0 : 1.0f - wA0)
                            * ((c & 2) ? wA1 : 1.0f - wA1)
                            * ((c & 4) ? wA2 : 1.0f - wA2);
            const float wtB = ((c & 1) ? wB0 : 1.0f - wB0)
                            * ((c & 2) ? wB1 : 1.0f - wB1)
                            * ((c & 4) ? wB2 : 1.0f - wB2);
            const float2 gA = __ldg(tbl + idxA);
            const float2 gB = __ldg(tbl + idxB);
            const u64 wtp = pack2(wtA, wtB);
            a0 = ffma2(wtp, pack2(gA.x, gB.x), a0);
            a1 = ffma2(wtp, pack2(gA.y, gB.y), a1);
        }

        const u64* wr0 = &sW0[(3 + 2 * l) * 32];
        const u64* wr1 = &sW0[(4 + 2 * l) * 32];
        #pragma unroll
        for (int j = 0; j < HIDDEN; j++) {
            h[j] = ffma2(a0, wr0[j], ffma2(a1, wr1[j], h[j]));
        }
    }

    // ---- ELU on h (componentwise) ----
    #pragma unroll
    for (int j = 0; j < HIDDEN; j++) {
        float a, b;
        unpack2(h[j], a, b);
        a = a > 0.0f ? a : expm1f(a);
        b = b > 0.0f ? b : expm1f(b);
        h[j] = pack2(a, b);
    }

    // ---- layer 1 + output, no h2 array ----
    u64 o = pack2(sbout, sbout);
    #pragma unroll 4
    for (int j = 0; j < HIDDEN; j++) {
        u64 t = sb1[j];
        #pragma unroll
        for (int i = 0; i < HIDDEN; i++) {
            t = ffma2(h[i], sW1[i * 32 + j], t);
        }
        float a, b;
        unpack2(t, a, b);
        a = a > 0.0f ? a : expm1f(a);
        b = b > 0.0f ? b : expm1f(b);
        o = ffma2(pack2(a, b), sWout[j], o);
    }

    float oA, oB;
    unpack2(o, oA, oB);
    out[oiA] = oA;
    if (hasB) out[oiB] = oB;
}

extern "C" void kernel_launch(void* const* d_in, const int* in_sizes, int n_in,
                              void* d_out, int out_size)
{
    const float* x     = (const float*)d_in[0];
    const float* table = (const float*)d_in[1];
    const float* W0    = (const float*)d_in[2];
    const float* b0    = (const float*)d_in[3];
    const float* W1    = (const float*)d_in[4];
    const float* b1    = (const float*)d_in[5];
    const float* Wout  = (const float*)d_in[6];
    const float* bout  = (const float*)d_in[7];
    float* out = (float*)d_out;

    const int n = in_sizes[0] / 3;

    zero_counts_kernel<<<NCELLS / 4 / 1024, 1024>>>();
    hist_kernel<<<(n + 255) / 256, 256>>>(x, n);
    scan1_kernel<<<NPART, SCAN_BLK>>>();
    scan2_kernel<<<1, SCAN_BLK>>>();
    scan3_kernel<<<NPART, SCAN_BLK>>>();
    scatter_kernel<<<(n + 255) / 256, 256>>>(x, n);

    const int nchunk = (n + 255) / 256;
    field_fused_kernel<<<nchunk, 128>>>(
        table, W0, b0, W1, b1, Wout, bout, out, n);
}